// round 1
// baseline (speedup 1.0000x reference)
#include <cuda_runtime.h>
#include <cuda_bf16.h>
#include <math.h>

// Problem constants (shapes fixed by the reference)
#define MAXN   100000
#define Dm     128
#define Hh     8
#define HID    256
#define QK     64
#define Vv     64
#define PSI    256
#define OUT    128
#define CAT    (Hh*Vv)   // 512
#define CHUNK  512
#define MAXCH  ((MAXN + CHUNK - 1) / CHUNK + 4)   // 200

// ---------------- device scratch (static, allocation-free) ----------------
__device__ float g_q[(size_t)Hh * MAXN * QK];     // phi(q)
__device__ float g_k[(size_t)Hh * MAXN * QK];     // phi(k)
__device__ float g_v[(size_t)Hh * MAXN * Vv];     // v
__device__ float g_cat[(size_t)MAXN * CAT];       // concatenated heads
__device__ float g_kv[Hh * QK * Vv];              // reduced kv
__device__ float g_sumk[Hh * QK];                 // reduced sum_k
__device__ float g_kvp[(size_t)Hh * MAXCH * QK * Vv];  // per-chunk partial kv
__device__ float g_skp[(size_t)Hh * MAXCH * QK];       // per-chunk partial sumk

// ---------------------------------------------------------------------------
// Kernel A: fused per-head 2-layer MLP for q/k/v (+mask, +phi for q/k)
//   grid: (rowTiles, H, 3), block: 256 threads, dyn smem 80KB
// ---------------------------------------------------------------------------
__global__ void mlp_heads_kernel(
    const float* __restrict__ x, const float* __restrict__ mask,
    const float* __restrict__ Wq0, const float* __restrict__ bq0,
    const float* __restrict__ Wq1, const float* __restrict__ bq1,
    const float* __restrict__ Wk0, const float* __restrict__ bk0,
    const float* __restrict__ Wk1, const float* __restrict__ bk1,
    const float* __restrict__ Wv0, const float* __restrict__ bv0,
    const float* __restrict__ Wv1, const float* __restrict__ bv1,
    int n)
{
    extern __shared__ float sm[];
    const int tileR = blockIdx.x * 64;
    const int h     = blockIdx.y;
    const int proj  = blockIdx.z;   // 0=q, 1=k, 2=v

    const float *W0, *b0, *W1, *b1;
    if (proj == 0)      { W0 = Wq0; b0 = bq0; W1 = Wq1; b1 = bq1; }
    else if (proj == 1) { W0 = Wk0; b0 = bk0; W1 = Wk1; b1 = bk1; }
    else                { W0 = Wv0; b0 = bv0; W1 = Wv1; b1 = bv1; }
    W0 += (size_t)h * Dm * HID;  b0 += h * HID;
    W1 += (size_t)h * HID * QK;  b1 += h * QK;

    float* sX  = sm;            // [64][128]  = 8192 f
    float* sW0 = sm + 64*128;   // [32][256]  = 8192 f
    // phase 2 (after reuse):
    float* sH  = sm;            // [64][256]  = 16384 f
    float* sW1 = sm + 64*256;   // [64][64]   = 4096 f   (total 80KB)

    const int tid = threadIdx.x;
    const int tx = tid & 15, ty = tid >> 4;

    // load X tile (zero-pad)
    for (int i = tid; i < 64*128; i += 256) {
        int r = i >> 7, c = i & 127;
        int gr = tileR + r;
        sX[i] = (gr < n) ? x[(size_t)gr * Dm + c] : 0.f;
    }

    // ---- phase 1: hidden[64,256] = relu(X @ W0 + b0), accum in regs ----
    float acc[64];
    #pragma unroll
    for (int i = 0; i < 64; i++) acc[i] = 0.f;

    for (int kc = 0; kc < 4; kc++) {
        __syncthreads();
        for (int i = tid; i < 32*256; i += 256)
            sW0[i] = W0[(size_t)(kc*32 + (i >> 8)) * HID + (i & 255)];
        __syncthreads();
        #pragma unroll
        for (int k = 0; k < 32; k++) {
            float xv[4];
            #pragma unroll
            for (int i = 0; i < 4; i++) xv[i] = sX[(ty*4 + i)*128 + kc*32 + k];
            float wv[16];
            #pragma unroll
            for (int j = 0; j < 16; j++) wv[j] = sW0[k*256 + tx*16 + j];
            #pragma unroll
            for (int i = 0; i < 4; i++)
                #pragma unroll
                for (int j = 0; j < 16; j++)
                    acc[i*16 + j] = fmaf(xv[i], wv[j], acc[i*16 + j]);
        }
    }
    __syncthreads();
    // dump hidden (bias + relu) into smem
    #pragma unroll
    for (int i = 0; i < 4; i++)
        #pragma unroll
        for (int j = 0; j < 16; j++) {
            int r = ty*4 + i, c = tx*16 + j;
            sH[r*256 + c] = fmaxf(acc[i*16 + j] + b0[c], 0.f);
        }
    __syncthreads();

    // ---- phase 2: out[64,64] = hidden @ W1 ----
    float acc2[16];
    #pragma unroll
    for (int i = 0; i < 16; i++) acc2[i] = 0.f;

    for (int kc = 0; kc < 4; kc++) {
        for (int i = tid; i < 64*64; i += 256)
            sW1[i] = W1[(size_t)(kc*64 + (i >> 6)) * QK + (i & 63)];
        __syncthreads();
        #pragma unroll
        for (int k = 0; k < 64; k++) {
            float hv[4];
            #pragma unroll
            for (int i = 0; i < 4; i++) hv[i] = sH[(ty*4 + i)*256 + kc*64 + k];
            float wv[4];
            #pragma unroll
            for (int j = 0; j < 4; j++) wv[j] = sW1[k*64 + tx*4 + j];
            #pragma unroll
            for (int i = 0; i < 4; i++)
                #pragma unroll
                for (int j = 0; j < 4; j++)
                    acc2[i*4 + j] = fmaf(hv[i], wv[j], acc2[i*4 + j]);
        }
        __syncthreads();
    }

    float* outBase = (proj == 0) ? g_q : (proj == 1) ? g_k : g_v;
    #pragma unroll
    for (int i = 0; i < 4; i++) {
        int r = ty*4 + i;
        int gr = tileR + r;
        if (gr >= n) continue;
        float m = mask[gr];
        #pragma unroll
        for (int j = 0; j < 4; j++) {
            int c = tx*4 + j;
            float val = (acc2[i*4 + j] + b1[c]) * m;
            if (proj < 2)  // phi = elu + 1
                val = (val > 0.f) ? (val + 1.f) : __expf(val);
            outBase[(size_t)h * n * QK + (size_t)gr * QK + c] = val;
        }
    }
}

// ---------------------------------------------------------------------------
// Kernel B: per-chunk partial kv = phi(k)^T v and partial sumk (deterministic)
//   grid: (nch, H), block 256
// ---------------------------------------------------------------------------
__global__ void kv_partial_kernel(int n)
{
    const int h = blockIdx.y;
    const int ch = blockIdx.x;
    const int chunk0 = ch * CHUNK;
    const int end = min(chunk0 + CHUNK, n);
    const float* kp = g_k + (size_t)h * n * QK;
    const float* vp = g_v + (size_t)h * n * Vv;

    __shared__ float sK[32*64], sV[32*64];
    const int tid = threadIdx.x;
    const int tx = tid & 15, ty = tid >> 4;

    float acc[16];
    #pragma unroll
    for (int i = 0; i < 16; i++) acc[i] = 0.f;
    float sumAcc = 0.f;

    for (int t0 = chunk0; t0 < end; t0 += 32) {
        __syncthreads();
        for (int i = tid; i < 32*64; i += 256) {
            int r = t0 + (i >> 6);
            int c = i & 63;
            if (r < end) {
                sK[i] = kp[(size_t)r * QK + c];
                sV[i] = vp[(size_t)r * Vv + c];
            } else {
                sK[i] = 0.f; sV[i] = 0.f;
            }
        }
        __syncthreads();
        #pragma unroll
        for (int r = 0; r < 32; r++) {
            float kk[4], vv[4];
            #pragma unroll
            for (int i = 0; i < 4; i++) kk[i] = sK[r*64 + ty*4 + i];
            #pragma unroll
            for (int j = 0; j < 4; j++) vv[j] = sV[r*64 + tx*4 + j];
            #pragma unroll
            for (int i = 0; i < 4; i++)
                #pragma unroll
                for (int j = 0; j < 4; j++)
                    acc[i*4 + j] = fmaf(kk[i], vv[j], acc[i*4 + j]);
        }
        if (tid < 64) {
            #pragma unroll
            for (int r = 0; r < 32; r++) sumAcc += sK[r*64 + tid];
        }
    }

    float* kvp = g_kvp + ((size_t)h * MAXCH + ch) * (QK * Vv);
    #pragma unroll
    for (int i = 0; i < 4; i++)
        #pragma unroll
        for (int j = 0; j < 4; j++)
            kvp[(ty*4 + i)*64 + tx*4 + j] = acc[i*4 + j];
    if (tid < 64)
        g_skp[((size_t)h * MAXCH + ch) * QK + tid] = sumAcc;
}

// Kernel R: fixed-order reduction of partials -> g_kv, g_sumk
__global__ void kv_reduce_kernel(int nch)
{
    const int h = blockIdx.x;
    const int tid = threadIdx.x;
    for (int c = tid; c < QK*Vv; c += blockDim.x) {
        float s = 0.f;
        for (int j = 0; j < nch; j++)
            s += g_kvp[((size_t)h * MAXCH + j) * (QK*Vv) + c];
        g_kv[h * QK*Vv + c] = s;
    }
    for (int c = tid; c < QK; c += blockDim.x) {
        float s = 0.f;
        for (int j = 0; j < nch; j++)
            s += g_skp[((size_t)h * MAXCH + j) * QK + c];
        g_sumk[h * QK + c] = s;
    }
}

// ---------------------------------------------------------------------------
// Kernel C: num = phi(q) @ kv ; den = phi(q) . sumk ; cat = num/den
//   grid: (rowTiles, H), block 256
// ---------------------------------------------------------------------------
__global__ void attn_out_kernel(int n)
{
    const int h = blockIdx.y;
    const int tileR = blockIdx.x * 64;
    const float* qp = g_q + (size_t)h * n * QK;

    __shared__ float sQ[64*64], sKV[64*64], sSum[64], sDen[64];
    const int tid = threadIdx.x;
    const int tx = tid & 15, ty = tid >> 4;

    for (int i = tid; i < 64*64; i += 256)
        sKV[i] = g_kv[h * QK*Vv + i];
    if (tid < 64) sSum[tid] = g_sumk[h * QK + tid];
    for (int i = tid; i < 64*64; i += 256) {
        int r = tileR + (i >> 6);
        sQ[i] = (r < n) ? qp[(size_t)r * QK + (i & 63)] : 0.f;
    }
    __syncthreads();

    if (tid < 64) {
        float d = 0.f;
        #pragma unroll
        for (int c = 0; c < 64; c++) d = fmaf(sQ[tid*64 + c], sSum[c], d);
        sDen[tid] = (d == 0.f) ? 1e-6f : d;
    }
    __syncthreads();

    float acc[16];
    #pragma unroll
    for (int i = 0; i < 16; i++) acc[i] = 0.f;
    #pragma unroll
    for (int k = 0; k < 64; k++) {
        float qv[4];
        #pragma unroll
        for (int i = 0; i < 4; i++) qv[i] = sQ[(ty*4 + i)*64 + k];
        float wv[4];
        #pragma unroll
        for (int j = 0; j < 4; j++) wv[j] = sKV[k*64 + tx*4 + j];
        #pragma unroll
        for (int i = 0; i < 4; i++)
            #pragma unroll
            for (int j = 0; j < 4; j++)
                acc[i*4 + j] = fmaf(qv[i], wv[j], acc[i*4 + j]);
    }

    #pragma unroll
    for (int i = 0; i < 4; i++) {
        int gr = tileR + ty*4 + i;
        if (gr >= n) continue;
        float invd = 1.f / sDen[ty*4 + i];
        #pragma unroll
        for (int j = 0; j < 4; j++)
            g_cat[(size_t)gr * CAT + h * Vv + tx*4 + j] = acc[i*4 + j] * invd;
    }
}

// ---------------------------------------------------------------------------
// Kernel D: out = relu(cat @ Wp0 + bp0) @ Wp1 + bp1, * mask
//   grid: rowTiles, block 256, dyn smem 96KB
// ---------------------------------------------------------------------------
__global__ void psi_kernel(
    const float* __restrict__ Wp0, const float* __restrict__ bp0,
    const float* __restrict__ Wp1, const float* __restrict__ bp1,
    const float* __restrict__ mask, float* __restrict__ out, int n)
{
    extern __shared__ float sm[];
    const int tileR = blockIdx.x * 64;
    const int tid = threadIdx.x;
    const int tx = tid & 15, ty = tid >> 4;

    float* sC  = sm;             // [64][32]  = 2048 f  (phase 1)
    float* sW0 = sm + 2048;      // [32][256] = 8192 f  (phase 1)
    float* sH  = sm;             // [64][256] = 16384 f (phase 2)
    float* sW1 = sm + 16384;     // [64][128] = 8192 f  (phase 2) -> 96KB total

    // ---- phase 1: hidden[64,256] = relu(cat @ Wp0 + bp0) ----
    float acc[64];
    #pragma unroll
    for (int i = 0; i < 64; i++) acc[i] = 0.f;

    for (int kc = 0; kc < 16; kc++) {
        __syncthreads();
        for (int i = tid; i < 64*32; i += 256) {
            int r = tileR + (i >> 5);
            sC[i] = (r < n) ? g_cat[(size_t)r * CAT + kc*32 + (i & 31)] : 0.f;
        }
        for (int i = tid; i < 32*256; i += 256)
            sW0[i] = Wp0[(size_t)(kc*32 + (i >> 8)) * PSI + (i & 255)];
        __syncthreads();
        #pragma unroll
        for (int k = 0; k < 32; k++) {
            float xv[4];
            #pragma unroll
            for (int i = 0; i < 4; i++) xv[i] = sC[(ty*4 + i)*32 + k];
            float wv[16];
            #pragma unroll
            for (int j = 0; j < 16; j++) wv[j] = sW0[k*256 + tx*16 + j];
            #pragma unroll
            for (int i = 0; i < 4; i++)
                #pragma unroll
                for (int j = 0; j < 16; j++)
                    acc[i*16 + j] = fmaf(xv[i], wv[j], acc[i*16 + j]);
        }
    }
    __syncthreads();
    #pragma unroll
    for (int i = 0; i < 4; i++)
        #pragma unroll
        for (int j = 0; j < 16; j++) {
            int r = ty*4 + i, c = tx*16 + j;
            sH[r*256 + c] = fmaxf(acc[i*16 + j] + bp0[c], 0.f);
        }
    __syncthreads();

    // ---- phase 2: out[64,128] = hidden @ Wp1 + bp1 ----
    float acc2[32];
    #pragma unroll
    for (int i = 0; i < 32; i++) acc2[i] = 0.f;

    for (int kc = 0; kc < 4; kc++) {
        for (int i = tid; i < 64*128; i += 256)
            sW1[i] = Wp1[(size_t)(kc*64 + (i >> 7)) * OUT + (i & 127)];
        __syncthreads();
        #pragma unroll
        for (int k = 0; k < 64; k++) {
            float hv[4];
            #pragma unroll
            for (int i = 0; i < 4; i++) hv[i] = sH[(ty*4 + i)*256 + kc*64 + k];
            float wv[8];
            #pragma unroll
            for (int j = 0; j < 8; j++) wv[j] = sW1[k*128 + tx*8 + j];
            #pragma unroll
            for (int i = 0; i < 4; i++)
                #pragma unroll
                for (int j = 0; j < 8; j++)
                    acc2[i*8 + j] = fmaf(hv[i], wv[j], acc2[i*8 + j]);
        }
        __syncthreads();
    }

    #pragma unroll
    for (int i = 0; i < 4; i++) {
        int gr = tileR + ty*4 + i;
        if (gr >= n) continue;
        float m = mask[gr];
        #pragma unroll
        for (int j = 0; j < 8; j++) {
            int c = tx*8 + j;
            out[(size_t)gr * OUT + c] = (acc2[i*8 + j] + bp1[c]) * m;
        }
    }
}

// ---------------------------------------------------------------------------
extern "C" void kernel_launch(void* const* d_in, const int* in_sizes, int n_in,
                              void* d_out, int out_size)
{
    const float* x    = (const float*)d_in[0];
    const float* mask = (const float*)d_in[1];
    const float* Wq0 = (const float*)d_in[2];
    const float* bq0 = (const float*)d_in[3];
    const float* Wq1 = (const float*)d_in[4];
    const float* bq1 = (const float*)d_in[5];
    const float* Wk0 = (const float*)d_in[6];
    const float* bk0 = (const float*)d_in[7];
    const float* Wk1 = (const float*)d_in[8];
    const float* bk1 = (const float*)d_in[9];
    const float* Wv0 = (const float*)d_in[10];
    const float* bv0 = (const float*)d_in[11];
    const float* Wv1 = (const float*)d_in[12];
    const float* bv1 = (const float*)d_in[13];
    const float* Wp0 = (const float*)d_in[14];
    const float* bp0 = (const float*)d_in[15];
    const float* Wp1 = (const float*)d_in[16];
    const float* bp1 = (const float*)d_in[17];
    float* out = (float*)d_out;

    const int n = in_sizes[0] / Dm;
    const int tiles = (n + 63) / 64;
    const int nch = (n + CHUNK - 1) / CHUNK;

    static int attr_done = 0;
    if (!attr_done) {
        cudaFuncSetAttribute(mlp_heads_kernel,
            cudaFuncAttributeMaxDynamicSharedMemorySize, 80 * 1024);
        cudaFuncSetAttribute(psi_kernel,
            cudaFuncAttributeMaxDynamicSharedMemorySize, 96 * 1024);
        attr_done = 1;
    }

    mlp_heads_kernel<<<dim3(tiles, Hh, 3), 256, 80 * 1024>>>(
        x, mask, Wq0, bq0, Wq1, bq1, Wk0, bk0, Wk1, bk1, Wv0, bv0, Wv1, bv1, n);
    kv_partial_kernel<<<dim3(nch, Hh), 256>>>(n);
    kv_reduce_kernel<<<Hh, 256>>>(nch);
    attn_out_kernel<<<dim3(tiles, Hh), 256>>>(n);
    psi_kernel<<<tiles, 256, 96 * 1024>>>(Wp0, bp0, Wp1, bp1, mask, out, n);
}

// round 3
// speedup vs baseline: 1.6186x; 1.6186x over previous
#include <cuda_runtime.h>
#include <cuda_bf16.h>
#include <math.h>
#include <stdint.h>

// Problem constants (fixed shapes)
#define MAXN   100000
#define Dm     128
#define Hh     8
#define HID    256
#define QK     64
#define Vv     64
#define PSI    256
#define OUT    128
#define CAT    (Hh*Vv)   // 512
#define CHUNK  512
#define MAXCH  ((MAXN + CHUNK - 1) / CHUNK + 4)   // 200

// ---------------- device scratch (static, allocation-free) ----------------
__device__ __align__(16) float g_q[(size_t)Hh * MAXN * QK];     // phi(q)
__device__ __align__(16) float g_k[(size_t)Hh * MAXN * QK];     // phi(k)
__device__ __align__(16) float g_v[(size_t)Hh * MAXN * Vv];     // v
__device__ __align__(16) float g_cat[(size_t)MAXN * CAT];       // concatenated heads
__device__ __align__(16) float g_kv[Hh * QK * Vv];
__device__ __align__(16) float g_sumk[Hh * QK];
__device__ __align__(16) float g_kvp[(size_t)Hh * MAXCH * QK * Vv];
__device__ __align__(16) float g_skp[(size_t)Hh * MAXCH * QK];

// split+swizzled weights (hi/lo tf32 interleaved, fragment-ready)
__device__ __align__(16) float g_w0s[24 * 128 * 256 * 2];   // per (proj,h): K=128,N=256
__device__ __align__(16) float g_w1s[24 * 256 * 64 * 2];    // per (proj,h): K=256,N=64
__device__ __align__(16) float g_p0s[512 * 256 * 2];        // K=512,N=256
__device__ __align__(16) float g_p1s[256 * 128 * 2];        // K=256,N=128

// ---------------------------------------------------------------------------
__device__ __forceinline__ float to_tf32(float x) {
    uint32_t u;
    asm("cvt.rna.tf32.f32 %0, %1;" : "=r"(u) : "f"(x));
    return __uint_as_float(u);
}

__device__ __forceinline__ void mma8(float& c0, float& c1, float& c2, float& c3,
                                     float a0, float a1, float a2, float a3,
                                     float b0, float b1) {
    asm volatile(
        "mma.sync.aligned.m16n8k8.row.col.f32.tf32.tf32.f32 "
        "{%0,%1,%2,%3},{%4,%5,%6,%7},{%8,%9},{%0,%1,%2,%3};"
        : "+f"(c0), "+f"(c1), "+f"(c2), "+f"(c3)
        : "r"(__float_as_uint(a0)), "r"(__float_as_uint(a1)),
          "r"(__float_as_uint(a2)), "r"(__float_as_uint(a3)),
          "r"(__float_as_uint(b0)), "r"(__float_as_uint(b1)));
}

// Swizzled B index: ((k/8)*(N/8)+(n/8))*64 + (n%8)*8 + (k%8), x2 for hi/lo.
// ---------------------------------------------------------------------------
// prep: split all weights into hi/lo tf32 and swizzle into fragment layout
//   grid (32, 50), 256 threads
// ---------------------------------------------------------------------------
__global__ void prep_weights_kernel(
    const float* __restrict__ Wq0, const float* __restrict__ Wq1,
    const float* __restrict__ Wk0, const float* __restrict__ Wk1,
    const float* __restrict__ Wv0, const float* __restrict__ Wv1,
    const float* __restrict__ Wp0, const float* __restrict__ Wp1)
{
    int seg = blockIdx.y;
    const float* src; float* dst; int K, N;
    if (seg < 24) {
        int p = seg >> 3, h = seg & 7;
        src = (p == 0 ? Wq0 : p == 1 ? Wk0 : Wv0) + (size_t)h * 128 * 256;
        dst = g_w0s + (size_t)seg * (128 * 256 * 2); K = 128; N = 256;
    } else if (seg < 48) {
        int s = seg - 24; int p = s >> 3, h = s & 7;
        src = (p == 0 ? Wq1 : p == 1 ? Wk1 : Wv1) + (size_t)h * 256 * 64;
        dst = g_w1s + (size_t)s * (256 * 64 * 2); K = 256; N = 64;
    } else if (seg == 48) { src = Wp0; dst = g_p0s; K = 512; N = 256; }
    else                  { src = Wp1; dst = g_p1s; K = 256; N = 128; }

    int total = K * N;
    for (int e = blockIdx.x * 256 + threadIdx.x; e < total; e += 32 * 256) {
        int k = e / N, nn = e % N;
        float v = src[e];
        float hi = to_tf32(v), lo = to_tf32(v - hi);
        int sw = ((k >> 3) * (N >> 3) + (nn >> 3)) * 64 + (nn & 7) * 8 + (k & 7);
        dst[sw * 2]     = hi;
        dst[sw * 2 + 1] = lo;
    }
}

// ---------------------------------------------------------------------------
// mlp (tensor-core, 3xTF32): 32 rows/block, grid (n/32, H, 3), 256 thr, 96KB smem
// ---------------------------------------------------------------------------
__global__ void __launch_bounds__(256) mlp_tc_kernel(
    const float* __restrict__ x, const float* __restrict__ mask,
    const float* __restrict__ bq0, const float* __restrict__ bq1,
    const float* __restrict__ bk0, const float* __restrict__ bk1,
    const float* __restrict__ bv0, const float* __restrict__ bv1,
    int n)
{
    extern __shared__ float sm[];
    const int tileR = blockIdx.x * 32;
    const int h = blockIdx.y, proj = blockIdx.z;
    const float* b0 = (proj == 0 ? bq0 : proj == 1 ? bk0 : bv0) + h * HID;
    const float* b1 = (proj == 0 ? bq1 : proj == 1 ? bk1 : bv1) + h * QK;
    const float* w0s = g_w0s + (size_t)(proj * 8 + h) * (128 * 256 * 2);
    const float* w1s = g_w1s + (size_t)(proj * 8 + h) * (256 * 64 * 2);

    const int tid = threadIdx.x, w = tid >> 5, l = tid & 31;
    const int g = l >> 2, q4 = l & 3;

    float* sA  = sm;           // phase1: A frags [0,8192); phase2: A2 [0,16384)
    float* sW  = sm + 8192;    // phase1 W chunk [8192,24576)
    float* sW1 = sm + 16384;   // phase2 W chunk [16384,24576)

    // ---- stage X (split hi/lo, fragment layout) ----
    for (int e = tid; e < 32 * 128; e += 256) {
        int r = e >> 7, c = e & 127;
        int gr = tileR + r;
        float xv = (gr < n) ? x[(size_t)gr * Dm + c] : 0.f;
        float hi = to_tf32(xv), lo = to_tf32(xv - hi);
        int mt = r >> 4, rr = r & 15, kt = c >> 3, kk = c & 7;
        float* p = sA + ((mt * 16 + kt) << 8)
                      + (((rr & 7) << 2) + (kk & 3)) * 8
                      + (((rr >> 3) + ((kk >> 2) << 1)) << 1);
        p[0] = hi; p[1] = lo;
    }

    // ---- layer 1: C[32,256] = X[32,128] @ W0 ----
    float c1[2][4][4];
    #pragma unroll
    for (int a = 0; a < 2; a++)
        #pragma unroll
        for (int b = 0; b < 4; b++)
            #pragma unroll
            for (int c = 0; c < 4; c++) c1[a][b][c] = 0.f;

    for (int kc = 0; kc < 4; kc++) {
        __syncthreads();
        const float* srcw = w0s + kc * 16384;
        #pragma unroll
        for (int e = tid * 4; e < 16384; e += 1024)
            *(float4*)(sW + e) = *(const float4*)(srcw + e);
        __syncthreads();
        #pragma unroll
        for (int kt = 0; kt < 4; kt++) {
            int ktg = kc * 4 + kt;
            float4 f1[2], f2[2];
            #pragma unroll
            for (int mt = 0; mt < 2; mt++) {
                const float* ap = sA + ((mt * 16 + ktg) << 8) + l * 8;
                f1[mt] = *(const float4*)ap;
                f2[mt] = *(const float4*)(ap + 4);
            }
            #pragma unroll
            for (int j = 0; j < 4; j++) {
                const float* bp = sW + kt * 4096 + (w * 4 + j) * 128 + (g * 8 + q4) * 2;
                float2 b0v = *(const float2*)bp;
                float2 b1v = *(const float2*)(bp + 8);
                #pragma unroll
                for (int mt = 0; mt < 2; mt++) {
                    float* cc = c1[mt][j];
                    mma8(cc[0], cc[1], cc[2], cc[3],
                         f1[mt].x, f1[mt].z, f2[mt].x, f2[mt].z, b0v.x, b1v.x);
                    mma8(cc[0], cc[1], cc[2], cc[3],
                         f1[mt].y, f1[mt].w, f2[mt].y, f2[mt].w, b0v.x, b1v.x);
                    mma8(cc[0], cc[1], cc[2], cc[3],
                         f1[mt].x, f1[mt].z, f2[mt].x, f2[mt].z, b0v.y, b1v.y);
                }
            }
        }
    }

    // ---- epilogue L1: bias+relu, split, write A2 fragment layout ----
    __syncthreads();
    #pragma unroll
    for (int mt = 0; mt < 2; mt++)
        #pragma unroll
        for (int j = 0; j < 4; j++)
            #pragma unroll
            for (int idx = 0; idx < 4; idx++) {
                int row = mt * 16 + g + ((idx >> 1) << 3);
                int col = w * 32 + j * 8 + q4 * 2 + (idx & 1);
                float v = fmaxf(c1[mt][j][idx] + b0[col], 0.f);
                float hi = to_tf32(v), lo = to_tf32(v - hi);
                int kt2 = col >> 3, kk = col & 7, rr = row & 15;
                float* p = sA + (((row >> 4) * 32 + kt2) << 8)
                              + (((rr & 7) << 2) + (kk & 3)) * 8
                              + (((rr >> 3) + ((kk >> 2) << 1)) << 1);
                p[0] = hi; p[1] = lo;
            }

    // ---- layer 2: out[32,64] = H[32,256] @ W1 ----
    float c2[2][4];
    #pragma unroll
    for (int a = 0; a < 2; a++)
        #pragma unroll
        for (int b = 0; b < 4; b++) c2[a][b] = 0.f;

    for (int kc2 = 0; kc2 < 4; kc2++) {
        __syncthreads();
        const float* srcw = w1s + kc2 * 8192;
        #pragma unroll
        for (int e = tid * 4; e < 8192; e += 1024)
            *(float4*)(sW1 + e) = *(const float4*)(srcw + e);
        __syncthreads();
        #pragma unroll
        for (int kt = 0; kt < 8; kt++) {
            int ktg = kc2 * 8 + kt;
            float4 f1[2], f2[2];
            #pragma unroll
            for (int mt = 0; mt < 2; mt++) {
                const float* ap = sA + ((mt * 32 + ktg) << 8) + l * 8;
                f1[mt] = *(const float4*)ap;
                f2[mt] = *(const float4*)(ap + 4);
            }
            const float* bp = sW1 + kt * 1024 + w * 128 + (g * 8 + q4) * 2;
            float2 b0v = *(const float2*)bp;
            float2 b1v = *(const float2*)(bp + 8);
            #pragma unroll
            for (int mt = 0; mt < 2; mt++) {
                float* cc = c2[mt];
                mma8(cc[0], cc[1], cc[2], cc[3],
                     f1[mt].x, f1[mt].z, f2[mt].x, f2[mt].z, b0v.x, b1v.x);
                mma8(cc[0], cc[1], cc[2], cc[3],
                     f1[mt].y, f1[mt].w, f2[mt].y, f2[mt].w, b0v.x, b1v.x);
                mma8(cc[0], cc[1], cc[2], cc[3],
                     f1[mt].x, f1[mt].z, f2[mt].x, f2[mt].z, b0v.y, b1v.y);
            }
        }
    }

    // ---- epilogue L2: bias, mask, phi, store ----
    float* outBase = (proj == 0) ? g_q : (proj == 1) ? g_k : g_v;
    #pragma unroll
    for (int mt = 0; mt < 2; mt++)
        #pragma unroll
        for (int half = 0; half < 2; half++) {
            int row = mt * 16 + g + half * 8;
            int gr = tileR + row;
            if (gr >= n) continue;
            float m = mask[gr];
            int col = w * 8 + q4 * 2;
            float v0 = (c2[mt][half * 2 + 0] + b1[col])     * m;
            float v1 = (c2[mt][half * 2 + 1] + b1[col + 1]) * m;
            if (proj < 2) {
                v0 = (v0 > 0.f) ? (v0 + 1.f) : __expf(v0);
                v1 = (v1 > 0.f) ? (v1 + 1.f) : __expf(v1);
            }
            *(float2*)&outBase[((size_t)h * n + gr) * QK + col] = make_float2(v0, v1);
        }
}

// ---------------------------------------------------------------------------
// kv partial / reduce / attn (fp32, unchanged from passing baseline)
// ---------------------------------------------------------------------------
__global__ void kv_partial_kernel(int n)
{
    const int h = blockIdx.y;
    const int ch = blockIdx.x;
    const int chunk0 = ch * CHUNK;
    const int end = min(chunk0 + CHUNK, n);
    const float* kp = g_k + (size_t)h * n * QK;
    const float* vp = g_v + (size_t)h * n * Vv;

    __shared__ float sK[32 * 64], sV[32 * 64];
    const int tid = threadIdx.x;
    const int tx = tid & 15, ty = tid >> 4;

    float acc[16];
    #pragma unroll
    for (int i = 0; i < 16; i++) acc[i] = 0.f;
    float sumAcc = 0.f;

    for (int t0 = chunk0; t0 < end; t0 += 32) {
        __syncthreads();
        for (int i = tid; i < 32 * 64; i += 256) {
            int r = t0 + (i >> 6);
            int c = i & 63;
            if (r < end) { sK[i] = kp[(size_t)r * QK + c]; sV[i] = vp[(size_t)r * Vv + c]; }
            else         { sK[i] = 0.f; sV[i] = 0.f; }
        }
        __syncthreads();
        #pragma unroll
        for (int r = 0; r < 32; r++) {
            float kk[4], vv[4];
            #pragma unroll
            for (int i = 0; i < 4; i++) kk[i] = sK[r * 64 + ty * 4 + i];
            #pragma unroll
            for (int j = 0; j < 4; j++) vv[j] = sV[r * 64 + tx * 4 + j];
            #pragma unroll
            for (int i = 0; i < 4; i++)
                #pragma unroll
                for (int j = 0; j < 4; j++)
                    acc[i * 4 + j] = fmaf(kk[i], vv[j], acc[i * 4 + j]);
        }
        if (tid < 64) {
            #pragma unroll
            for (int r = 0; r < 32; r++) sumAcc += sK[r * 64 + tid];
        }
    }

    float* kvp = g_kvp + ((size_t)h * MAXCH + ch) * (QK * Vv);
    #pragma unroll
    for (int i = 0; i < 4; i++)
        #pragma unroll
        for (int j = 0; j < 4; j++)
            kvp[(ty * 4 + i) * 64 + tx * 4 + j] = acc[i * 4 + j];
    if (tid < 64)
        g_skp[((size_t)h * MAXCH + ch) * QK + tid] = sumAcc;
}

__global__ void kv_reduce_kernel(int nch)
{
    const int h = blockIdx.x;
    const int tid = threadIdx.x;
    for (int c = tid; c < QK * Vv; c += blockDim.x) {
        float s = 0.f;
        for (int j = 0; j < nch; j++)
            s += g_kvp[((size_t)h * MAXCH + j) * (QK * Vv) + c];
        g_kv[h * QK * Vv + c] = s;
    }
    for (int c = tid; c < QK; c += blockDim.x) {
        float s = 0.f;
        for (int j = 0; j < nch; j++)
            s += g_skp[((size_t)h * MAXCH + j) * QK + c];
        g_sumk[h * QK + c] = s;
    }
}

__global__ void attn_out_kernel(int n)
{
    const int h = blockIdx.y;
    const int tileR = blockIdx.x * 64;
    const float* qp = g_q + (size_t)h * n * QK;

    __shared__ float sQ[64 * 64], sKV[64 * 64], sSum[64], sDen[64];
    const int tid = threadIdx.x;
    const int tx = tid & 15, ty = tid >> 4;

    for (int i = tid; i < 64 * 64; i += 256)
        sKV[i] = g_kv[h * QK * Vv + i];
    if (tid < 64) sSum[tid] = g_sumk[h * QK + tid];
    for (int i = tid; i < 64 * 64; i += 256) {
        int r = tileR + (i >> 6);
        sQ[i] = (r < n) ? qp[(size_t)r * QK + (i & 63)] : 0.f;
    }
    __syncthreads();

    if (tid < 64) {
        float d = 0.f;
        #pragma unroll
        for (int c = 0; c < 64; c++) d = fmaf(sQ[tid * 64 + c], sSum[c], d);
        sDen[tid] = (d == 0.f) ? 1e-6f : d;
    }
    __syncthreads();

    float acc[16];
    #pragma unroll
    for (int i = 0; i < 16; i++) acc[i] = 0.f;
    #pragma unroll
    for (int k = 0; k < 64; k++) {
        float qv[4];
        #pragma unroll
        for (int i = 0; i < 4; i++) qv[i] = sQ[(ty * 4 + i) * 64 + k];
        float wv[4];
        #pragma unroll
        for (int j = 0; j < 4; j++) wv[j] = sKV[k * 64 + tx * 4 + j];
        #pragma unroll
        for (int i = 0; i < 4; i++)
            #pragma unroll
            for (int j = 0; j < 4; j++)
                acc[i * 4 + j] = fmaf(qv[i], wv[j], acc[i * 4 + j]);
    }

    #pragma unroll
    for (int i = 0; i < 4; i++) {
        int gr = tileR + ty * 4 + i;
        if (gr >= n) continue;
        float invd = 1.f / sDen[ty * 4 + i];
        #pragma unroll
        for (int j = 0; j < 4; j++)
            g_cat[(size_t)gr * CAT + h * Vv + tx * 4 + j] = acc[i * 4 + j] * invd;
    }
}

// ---------------------------------------------------------------------------
// psi (tensor-core, 3xTF32): 32 rows/block, 256 thr, 96KB smem
// ---------------------------------------------------------------------------
__global__ void __launch_bounds__(256) psi_tc_kernel(
    const float* __restrict__ bp0v, const float* __restrict__ bp1v,
    const float* __restrict__ mask, float* __restrict__ out, int n)
{
    extern __shared__ float sm[];
    const int tileR = blockIdx.x * 32;
    const int tid = threadIdx.x, w = tid >> 5, l = tid & 31;
    const int g = l >> 2, q4 = l & 3;

    float* sA  = sm;           // phase1 A chunk [0,8192); phase2 A2 [0,16384)
    float* sW  = sm + 8192;    // phase1 W chunk [8192,24576)
    float* sW1 = sm + 16384;   // phase2 W chunk [16384,24576)

    // ---- layer 1: H[32,256] = cat[32,512] @ Wp0 ----
    float c1[2][4][4];
    #pragma unroll
    for (int a = 0; a < 2; a++)
        #pragma unroll
        for (int b = 0; b < 4; b++)
            #pragma unroll
            for (int c = 0; c < 4; c++) c1[a][b][c] = 0.f;

    for (int kc = 0; kc < 4; kc++) {
        __syncthreads();
        // stage cat chunk (cols kc*128 .. +128) into fragment layout
        for (int e = tid; e < 32 * 128; e += 256) {
            int r = e >> 7, c = e & 127;
            int gr = tileR + r;
            float xv = (gr < n) ? g_cat[(size_t)gr * CAT + kc * 128 + c] : 0.f;
            float hi = to_tf32(xv), lo = to_tf32(xv - hi);
            int mt = r >> 4, rr = r & 15, kt = c >> 3, kk = c & 7;
            float* p = sA + ((mt * 16 + kt) << 8)
                          + (((rr & 7) << 2) + (kk & 3)) * 8
                          + (((rr >> 3) + ((kk >> 2) << 1)) << 1);
            p[0] = hi; p[1] = lo;
        }
        for (int kcc = 0; kcc < 4; kcc++) {
            __syncthreads();
            const float* srcw = g_p0s + (size_t)(kc * 16 + kcc * 4) * 4096;
            #pragma unroll
            for (int e = tid * 4; e < 16384; e += 1024)
                *(float4*)(sW + e) = *(const float4*)(srcw + e);
            __syncthreads();
            #pragma unroll
            for (int kt = 0; kt < 4; kt++) {
                int ktl = kcc * 4 + kt;
                float4 f1[2], f2[2];
                #pragma unroll
                for (int mt = 0; mt < 2; mt++) {
                    const float* ap = sA + ((mt * 16 + ktl) << 8) + l * 8;
                    f1[mt] = *(const float4*)ap;
                    f2[mt] = *(const float4*)(ap + 4);
                }
                #pragma unroll
                for (int j = 0; j < 4; j++) {
                    const float* bp = sW + kt * 4096 + (w * 4 + j) * 128 + (g * 8 + q4) * 2;
                    float2 b0v = *(const float2*)bp;
                    float2 b1v = *(const float2*)(bp + 8);
                    #pragma unroll
                    for (int mt = 0; mt < 2; mt++) {
                        float* cc = c1[mt][j];
                        mma8(cc[0], cc[1], cc[2], cc[3],
                             f1[mt].x, f1[mt].z, f2[mt].x, f2[mt].z, b0v.x, b1v.x);
                        mma8(cc[0], cc[1], cc[2], cc[3],
                             f1[mt].y, f1[mt].w, f2[mt].y, f2[mt].w, b0v.x, b1v.x);
                        mma8(cc[0], cc[1], cc[2], cc[3],
                             f1[mt].x, f1[mt].z, f2[mt].x, f2[mt].z, b0v.y, b1v.y);
                    }
                }
            }
        }
    }

    // ---- epilogue L1 -> A2 frags ----
    __syncthreads();
    #pragma unroll
    for (int mt = 0; mt < 2; mt++)
        #pragma unroll
        for (int j = 0; j < 4; j++)
            #pragma unroll
            for (int idx = 0; idx < 4; idx++) {
                int row = mt * 16 + g + ((idx >> 1) << 3);
                int col = w * 32 + j * 8 + q4 * 2 + (idx & 1);
                float v = fmaxf(c1[mt][j][idx] + bp0v[col], 0.f);
                float hi = to_tf32(v), lo = to_tf32(v - hi);
                int kt2 = col >> 3, kk = col & 7, rr = row & 15;
                float* p = sA + (((row >> 4) * 32 + kt2) << 8)
                              + (((rr & 7) << 2) + (kk & 3)) * 8
                              + (((rr >> 3) + ((kk >> 2) << 1)) << 1);
                p[0] = hi; p[1] = lo;
            }

    // ---- layer 2: out[32,128] = H[32,256] @ Wp1 ----
    float c2[2][2][4];
    #pragma unroll
    for (int a = 0; a < 2; a++)
        #pragma unroll
        for (int b = 0; b < 2; b++)
            #pragma unroll
            for (int c = 0; c < 4; c++) c2[a][b][c] = 0.f;

    for (int kc2 = 0; kc2 < 8; kc2++) {
        __syncthreads();
        const float* srcw = g_p1s + (size_t)kc2 * 8192;
        #pragma unroll
        for (int e = tid * 4; e < 8192; e += 1024)
            *(float4*)(sW1 + e) = *(const float4*)(srcw + e);
        __syncthreads();
        #pragma unroll
        for (int kt = 0; kt < 4; kt++) {
            int ktg = kc2 * 4 + kt;
            float4 f1[2], f2[2];
            #pragma unroll
            for (int mt = 0; mt < 2; mt++) {
                const float* ap = sA + ((mt * 32 + ktg) << 8) + l * 8;
                f1[mt] = *(const float4*)ap;
                f2[mt] = *(const float4*)(ap + 4);
            }
            #pragma unroll
            for (int jn = 0; jn < 2; jn++) {
                const float* bp = sW1 + kt * 2048 + (w * 2 + jn) * 128 + (g * 8 + q4) * 2;
                float2 b0v = *(const float2*)bp;
                float2 b1v = *(const float2*)(bp + 8);
                #pragma unroll
                for (int mt = 0; mt < 2; mt++) {
                    float* cc = c2[mt][jn];
                    mma8(cc[0], cc[1], cc[2], cc[3],
                         f1[mt].x, f1[mt].z, f2[mt].x, f2[mt].z, b0v.x, b1v.x);
                    mma8(cc[0], cc[1], cc[2], cc[3],
                         f1[mt].y, f1[mt].w, f2[mt].y, f2[mt].w, b0v.x, b1v.x);
                    mma8(cc[0], cc[1], cc[2], cc[3],
                         f1[mt].x, f1[mt].z, f2[mt].x, f2[mt].z, b0v.y, b1v.y);
                }
            }
        }
    }

    // ---- epilogue L2: bias, mask, store ----
    #pragma unroll
    for (int mt = 0; mt < 2; mt++)
        #pragma unroll
        for (int jn = 0; jn < 2; jn++)
            #pragma unroll
            for (int half = 0; half < 2; half++) {
                int row = mt * 16 + g + half * 8;
                int gr = tileR + row;
                if (gr >= n) continue;
                float m = mask[gr];
                int col = (w * 2 + jn) * 8 + q4 * 2;
                float v0 = (c2[mt][jn][half * 2 + 0] + bp1v[col])     * m;
                float v1 = (c2[mt][jn][half * 2 + 1] + bp1v[col + 1]) * m;
                *(float2*)&out[(size_t)gr * OUT + col] = make_float2(v0, v1);
            }
}

// ---------------------------------------------------------------------------
extern "C" void kernel_launch(void* const* d_in, const int* in_sizes, int n_in,
                              void* d_out, int out_size)
{
    const float* x    = (const float*)d_in[0];
    const float* mask = (const float*)d_in[1];
    const float* Wq0 = (const float*)d_in[2];
    const float* bq0 = (const float*)d_in[3];
    const float* Wq1 = (const float*)d_in[4];
    const float* bq1 = (const float*)d_in[5];
    const float* Wk0 = (const float*)d_in[6];
    const float* bk0 = (const float*)d_in[7];
    const float* Wk1 = (const float*)d_in[8];
    const float* bk1 = (const float*)d_in[9];
    const float* Wv0 = (const float*)d_in[10];
    const float* bv0 = (const float*)d_in[11];
    const float* Wv1 = (const float*)d_in[12];
    const float* bv1 = (const float*)d_in[13];
    const float* Wp0 = (const float*)d_in[14];
    const float* bp0 = (const float*)d_in[15];
    const float* Wp1 = (const float*)d_in[16];
    const float* bp1 = (const float*)d_in[17];
    float* out = (float*)d_out;

    const int n = in_sizes[0] / Dm;
    const int tiles32 = (n + 31) / 32;
    const int tiles64 = (n + 63) / 64;
    const int nch = (n + CHUNK - 1) / CHUNK;

    static int attr_done = 0;
    if (!attr_done) {
        cudaFuncSetAttribute(mlp_tc_kernel,
            cudaFuncAttributeMaxDynamicSharedMemorySize, 96 * 1024);
        cudaFuncSetAttribute(psi_tc_kernel,
            cudaFuncAttributeMaxDynamicSharedMemorySize, 96 * 1024);
        attr_done = 1;
    }

    prep_weights_kernel<<<dim3(32, 50), 256>>>(Wq0, Wq1, Wk0, Wk1, Wv0, Wv1, Wp0, Wp1);
    mlp_tc_kernel<<<dim3(tiles32, Hh, 3), 256, 96 * 1024>>>(
        x, mask, bq0, bq1, bk0, bk1, bv0, bv1, n);
    kv_partial_kernel<<<dim3(nch, Hh), 256>>>(n);
    kv_reduce_kernel<<<Hh, 256>>>(nch);
    attn_out_kernel<<<dim3(tiles64, Hh), 256>>>(n);
    psi_tc_kernel<<<tiles32, 256, 96 * 1024>>>(bp0, bp1, mask, out, n);
}

// round 4
// speedup vs baseline: 4.3917x; 2.7133x over previous
#include <cuda_runtime.h>
#include <cuda_bf16.h>
#include <math.h>
#include <stdint.h>

// Problem constants (fixed shapes)
#define MAXN   100000
#define Dm     128
#define Hh     8
#define HID    256
#define QK     64
#define Vv     64
#define PSI    256
#define OUT    128
#define CAT    (Hh*Vv)   // 512
#define CHUNK  512
#define MAXCH  ((MAXN + CHUNK - 1) / CHUNK + 4)   // 200

// ---------------- device scratch (static, allocation-free) ----------------
__device__ __align__(16) float g_q[(size_t)Hh * MAXN * QK];
__device__ __align__(16) float g_k[(size_t)Hh * MAXN * QK];
__device__ __align__(16) float g_v[(size_t)Hh * MAXN * Vv];
__device__ __align__(16) float g_cat[(size_t)MAXN * CAT];
__device__ __align__(16) float g_kv[Hh * QK * Vv];
__device__ __align__(16) float g_sumk[Hh * QK];
__device__ __align__(16) float g_kvp[(size_t)Hh * MAXCH * QK * Vv];
__device__ __align__(16) float g_skp[(size_t)Hh * MAXCH * QK];

// bf16 hi/lo split weights in fragment-ready tile layout.
// Tile = 16(k) x 8(n): 32 lanes x (2 u32 hi + 2 u32 lo) = 128 u32 = 512B.
// Tile order: (kt, nt) row-major. Per lane l: g=l>>2, q4=l&3;
//   hi reg0 = (W[k0+2q4, n0+g], W[k0+2q4+1, n0+g]), reg1 = rows +8.
__device__ __align__(16) uint32_t g_w0s[24 * 8 * 32 * 128];   // K=128,N=256 per (proj,h)
__device__ __align__(16) uint32_t g_w1s[24 * 16 * 8 * 128];   // K=256,N=64
__device__ __align__(16) uint32_t g_p0s[32 * 32 * 128];       // K=512,N=256
__device__ __align__(16) uint32_t g_p1s[16 * 16 * 128];       // K=256,N=128

// ---------------------------------------------------------------------------
__device__ __forceinline__ void split_pair(float a, float b, uint32_t& hi, uint32_t& lo) {
    __nv_bfloat16 ah = __float2bfloat16_rn(a), bh = __float2bfloat16_rn(b);
    float ar = a - __bfloat162float(ah);
    float br = b - __bfloat162float(bh);
    hi = ((uint32_t)__bfloat16_as_ushort(bh) << 16) | (uint32_t)__bfloat16_as_ushort(ah);
    __nv_bfloat16 al = __float2bfloat16_rn(ar), bl = __float2bfloat16_rn(br);
    lo = ((uint32_t)__bfloat16_as_ushort(bl) << 16) | (uint32_t)__bfloat16_as_ushort(al);
}

__device__ __forceinline__ void mmabf(float* c, const uint4& a, const uint2& b) {
    asm volatile(
        "mma.sync.aligned.m16n8k16.row.col.f32.bf16.bf16.f32 "
        "{%0,%1,%2,%3},{%4,%5,%6,%7},{%8,%9},{%0,%1,%2,%3};"
        : "+f"(c[0]), "+f"(c[1]), "+f"(c[2]), "+f"(c[3])
        : "r"(a.x), "r"(a.y), "r"(a.z), "r"(a.w), "r"(b.x), "r"(b.y));
}

// ---------------------------------------------------------------------------
// prep: split weights into bf16 hi/lo fragment tiles.  grid (128, 50), 256 thr
// ---------------------------------------------------------------------------
__global__ void prep_weights_kernel(
    const float* __restrict__ Wq0, const float* __restrict__ Wq1,
    const float* __restrict__ Wk0, const float* __restrict__ Wk1,
    const float* __restrict__ Wv0, const float* __restrict__ Wv1,
    const float* __restrict__ Wp0, const float* __restrict__ Wp1)
{
    int seg = blockIdx.y;
    const float* src; uint32_t* dst; int K, N;
    if (seg < 24) {
        int p = seg >> 3, h = seg & 7;
        src = (p == 0 ? Wq0 : p == 1 ? Wk0 : Wv0) + (size_t)h * 128 * 256;
        dst = g_w0s + (size_t)seg * (8 * 32 * 128); K = 128; N = 256;
    } else if (seg < 48) {
        int s = seg - 24; int p = s >> 3, h = s & 7;
        src = (p == 0 ? Wq1 : p == 1 ? Wk1 : Wv1) + (size_t)h * 256 * 64;
        dst = g_w1s + (size_t)s * (16 * 8 * 128); K = 256; N = 64;
    } else if (seg == 48) { src = Wp0; dst = g_p0s; K = 512; N = 256; }
    else                  { src = Wp1; dst = g_p1s; K = 256; N = 128; }

    int nslots = (K >> 4) * (N >> 3) * 32;
    int s = blockIdx.x * 256 + threadIdx.x;
    if (s >= nslots) return;
    int tile = s >> 5, l = s & 31;
    int ntT = N >> 3;
    int kt = tile / ntT, nt = tile % ntT;
    int g = l >> 2, q4 = l & 3;
    int k0 = kt * 16 + 2 * q4, nn = nt * 8 + g;
    float e00 = src[(size_t)k0 * N + nn];
    float e01 = src[(size_t)(k0 + 1) * N + nn];
    float e10 = src[(size_t)(k0 + 8) * N + nn];
    float e11 = src[(size_t)(k0 + 9) * N + nn];
    uint32_t h0, l0, h1, l1;
    split_pair(e00, e01, h0, l0);
    split_pair(e10, e11, h1, l1);
    uint32_t* t = dst + (size_t)tile * 128;
    t[l * 2]          = h0;
    t[l * 2 + 1]      = h1;
    t[64 + l * 2]     = l0;
    t[64 + l * 2 + 1] = l1;
}

// ---------------------------------------------------------------------------
// Stage a 64x128 fp32 chunk into A-fragment tiles (bf16 hi/lo).
// A region: tile (mt,ktl) at (mt*8+ktl)*256 u32; hi lane*4+reg, lo +128.
// ---------------------------------------------------------------------------
__device__ __forceinline__ void stage_A64x128(
    uint32_t* sA, const float* __restrict__ src, size_t rowStride,
    int tileR, int colOff, int n, int tid)
{
    for (int e = tid; e < 64 * 64; e += 256) {
        int r = e >> 6, cp = e & 63;
        int c = cp * 2;
        int gr = tileR + r;
        float x0 = 0.f, x1 = 0.f;
        if (gr < n) {
            const float* p = src + (size_t)gr * rowStride + colOff + c;
            x0 = p[0]; x1 = p[1];
        }
        uint32_t hi, lo;
        split_pair(x0, x1, hi, lo);
        int mt = r >> 4, kt = c >> 4, rr = r & 15, kk = c & 15;
        int lane = (rr & 7) * 4 + ((kk & 7) >> 1);
        int reg  = (kk >= 8 ? 2 : 0) + (rr >= 8 ? 1 : 0);
        uint32_t* tb = sA + (mt * 8 + kt) * 256 + lane * 4 + reg;
        tb[0]   = hi;
        tb[128] = lo;
    }
}

// ---------------------------------------------------------------------------
// mlp: 64 rows/block, grid (ceil(n/64), H, 3), 256 thr, 96KB smem
// ---------------------------------------------------------------------------
__global__ void __launch_bounds__(256, 2) mlp_tc_kernel(
    const float* __restrict__ x, const float* __restrict__ mask,
    const float* __restrict__ bq0, const float* __restrict__ bq1,
    const float* __restrict__ bk0, const float* __restrict__ bk1,
    const float* __restrict__ bv0, const float* __restrict__ bv1,
    int n)
{
    extern __shared__ uint32_t sm[];
    uint32_t* sA = sm;            // [0,16384) u32 : A frags / A2 frags
    uint32_t* sW = sm + 16384;    // [16384,24576) : 32KB weight chunk

    const int tileR = blockIdx.x * 64;
    const int h = blockIdx.y, proj = blockIdx.z;
    const float* b0 = (proj == 0 ? bq0 : proj == 1 ? bk0 : bv0) + h * HID;
    const float* b1 = (proj == 0 ? bq1 : proj == 1 ? bk1 : bv1) + h * QK;
    const uint32_t* w0s = g_w0s + (size_t)(proj * 8 + h) * (8 * 32 * 128);
    const uint32_t* w1s = g_w1s + (size_t)(proj * 8 + h) * (16 * 8 * 128);

    const int tid = threadIdx.x, w = tid >> 5, l = tid & 31;
    const int g = l >> 2, q4 = l & 3;

    stage_A64x128(sA, x, Dm, tileR, 0, n, tid);

    // ---- layer 1: C[64,256] = X[64,128] @ W0 ----
    float c1[4][4][4];
    #pragma unroll
    for (int a = 0; a < 4; a++)
        #pragma unroll
        for (int b = 0; b < 4; b++)
            #pragma unroll
            for (int c = 0; c < 4; c++) c1[a][b][c] = 0.f;

    for (int kc = 0; kc < 4; kc++) {
        __syncthreads();
        const uint32_t* srcw = w0s + kc * 8192;          // 2 kt x 32 nt
        #pragma unroll
        for (int e = tid * 4; e < 8192; e += 1024)
            *(uint4*)(sW + e) = *(const uint4*)(srcw + e);
        __syncthreads();
        #pragma unroll
        for (int kt2 = 0; kt2 < 2; kt2++) {
            int ktg = kc * 2 + kt2;
            uint2 bh[4], bl[4];
            #pragma unroll
            for (int j = 0; j < 4; j++) {
                const uint32_t* bb = sW + (kt2 * 32 + w * 4 + j) * 128 + l * 2;
                bh[j] = *(const uint2*)bb;
                bl[j] = *(const uint2*)(bb + 64);
            }
            #pragma unroll
            for (int mt = 0; mt < 4; mt++) {
                const uint32_t* ab = sA + (mt * 8 + ktg) * 256 + l * 4;
                uint4 ah = *(const uint4*)ab;
                uint4 al = *(const uint4*)(ab + 128);
                #pragma unroll
                for (int j = 0; j < 4; j++) {
                    mmabf(c1[mt][j], ah, bh[j]);
                    mmabf(c1[mt][j], al, bh[j]);
                    mmabf(c1[mt][j], ah, bl[j]);
                }
            }
        }
    }

    // ---- epilogue L1: bias+relu, split, write A2 frags ----
    __syncthreads();
    #pragma unroll
    for (int mt = 0; mt < 4; mt++)
        #pragma unroll
        for (int j = 0; j < 4; j++) {
            int col0 = w * 32 + j * 8 + 2 * q4;
            float bv0 = b0[col0], bv1 = b0[col0 + 1];
            float v00 = fmaxf(c1[mt][j][0] + bv0, 0.f);
            float v01 = fmaxf(c1[mt][j][1] + bv1, 0.f);
            float v10 = fmaxf(c1[mt][j][2] + bv0, 0.f);
            float v11 = fmaxf(c1[mt][j][3] + bv1, 0.f);
            uint32_t h0, l0v, h1, l1v;
            split_pair(v00, v01, h0, l0v);
            split_pair(v10, v11, h1, l1v);
            int kt2 = w * 2 + (j >> 1);
            int rb = (j & 1) * 2;
            uint32_t* tb = sA + (mt * 16 + kt2) * 256 + l * 4;
            tb[rb]         = h0;
            tb[rb + 1]     = h1;
            tb[128 + rb]     = l0v;
            tb[128 + rb + 1] = l1v;
        }

    // ---- layer 2: out[64,64] = H[64,256] @ W1 ----
    float c2[4][4];
    #pragma unroll
    for (int a = 0; a < 4; a++)
        #pragma unroll
        for (int b = 0; b < 4; b++) c2[a][b] = 0.f;

    for (int kc = 0; kc < 2; kc++) {
        __syncthreads();
        const uint32_t* srcw = w1s + kc * 8192;          // 8 kt x 8 nt
        #pragma unroll
        for (int e = tid * 4; e < 8192; e += 1024)
            *(uint4*)(sW + e) = *(const uint4*)(srcw + e);
        __syncthreads();
        #pragma unroll
        for (int kt = 0; kt < 8; kt++) {
            int ktg = kc * 8 + kt;
            const uint32_t* bb = sW + (kt * 8 + w) * 128 + l * 2;
            uint2 bh = *(const uint2*)bb;
            uint2 bl = *(const uint2*)(bb + 64);
            #pragma unroll
            for (int mt = 0; mt < 4; mt++) {
                const uint32_t* ab = sA + (mt * 16 + ktg) * 256 + l * 4;
                uint4 ah = *(const uint4*)ab;
                uint4 al = *(const uint4*)(ab + 128);
                mmabf(c2[mt], ah, bh);
                mmabf(c2[mt], al, bh);
                mmabf(c2[mt], ah, bl);
            }
        }
    }

    // ---- epilogue L2: bias, mask, phi, store ----
    float* outBase = (proj == 0) ? g_q : (proj == 1) ? g_k : g_v;
    int col0 = w * 8 + 2 * q4;
    float bb0 = b1[col0], bb1 = b1[col0 + 1];
    #pragma unroll
    for (int mt = 0; mt < 4; mt++)
        #pragma unroll
        for (int half = 0; half < 2; half++) {
            int gr = tileR + mt * 16 + g + half * 8;
            if (gr >= n) continue;
            float m = mask[gr];
            float v0 = (c2[mt][half * 2 + 0] + bb0) * m;
            float v1 = (c2[mt][half * 2 + 1] + bb1) * m;
            if (proj < 2) {
                v0 = (v0 > 0.f) ? (v0 + 1.f) : __expf(v0);
                v1 = (v1 > 0.f) ? (v1 + 1.f) : __expf(v1);
            }
            *(float2*)&outBase[((size_t)h * n + gr) * QK + col0] = make_float2(v0, v1);
        }
}

// ---------------------------------------------------------------------------
// kv partial (fp32) / reduce / attn (fp32) — proven-correct path
// ---------------------------------------------------------------------------
__global__ void kv_partial_kernel(int n)
{
    const int h = blockIdx.y;
    const int ch = blockIdx.x;
    const int chunk0 = ch * CHUNK;
    const int end = min(chunk0 + CHUNK, n);
    const float* kp = g_k + (size_t)h * n * QK;
    const float* vp = g_v + (size_t)h * n * Vv;

    __shared__ float sK[32 * 64], sV[32 * 64];
    const int tid = threadIdx.x;
    const int tx = tid & 15, ty = tid >> 4;

    float acc[16];
    #pragma unroll
    for (int i = 0; i < 16; i++) acc[i] = 0.f;
    float sumAcc = 0.f;

    for (int t0 = chunk0; t0 < end; t0 += 32) {
        __syncthreads();
        for (int i = tid; i < 32 * 64; i += 256) {
            int r = t0 + (i >> 6);
            int c = i & 63;
            if (r < end) { sK[i] = kp[(size_t)r * QK + c]; sV[i] = vp[(size_t)r * Vv + c]; }
            else         { sK[i] = 0.f; sV[i] = 0.f; }
        }
        __syncthreads();
        #pragma unroll
        for (int r = 0; r < 32; r++) {
            float kk[4], vv[4];
            #pragma unroll
            for (int i = 0; i < 4; i++) kk[i] = sK[r * 64 + ty * 4 + i];
            #pragma unroll
            for (int j = 0; j < 4; j++) vv[j] = sV[r * 64 + tx * 4 + j];
            #pragma unroll
            for (int i = 0; i < 4; i++)
                #pragma unroll
                for (int j = 0; j < 4; j++)
                    acc[i * 4 + j] = fmaf(kk[i], vv[j], acc[i * 4 + j]);
        }
        if (tid < 64) {
            #pragma unroll
            for (int r = 0; r < 32; r++) sumAcc += sK[r * 64 + tid];
        }
    }

    float* kvp = g_kvp + ((size_t)h * MAXCH + ch) * (QK * Vv);
    #pragma unroll
    for (int i = 0; i < 4; i++)
        #pragma unroll
        for (int j = 0; j < 4; j++)
            kvp[(ty * 4 + i) * 64 + tx * 4 + j] = acc[i * 4 + j];
    if (tid < 64)
        g_skp[((size_t)h * MAXCH + ch) * QK + tid] = sumAcc;
}

// grid (Hh, 33), 128 threads
__global__ void kv_reduce_kernel(int nch)
{
    const int h = blockIdx.x;
    const int c = blockIdx.y * 128 + threadIdx.x;
    if (c < QK * Vv) {
        float s = 0.f;
        for (int j = 0; j < nch; j++)
            s += g_kvp[((size_t)h * MAXCH + j) * (QK * Vv) + c];
        g_kv[h * QK * Vv + c] = s;
    } else if (c < QK * Vv + QK) {
        int cc = c - QK * Vv;
        float s = 0.f;
        for (int j = 0; j < nch; j++)
            s += g_skp[((size_t)h * MAXCH + j) * QK + cc];
        g_sumk[h * QK + cc] = s;
    }
}

__global__ void attn_out_kernel(int n)
{
    const int h = blockIdx.y;
    const int tileR = blockIdx.x * 64;
    const float* qp = g_q + (size_t)h * n * QK;

    __shared__ float sQ[64 * 64], sKV[64 * 64], sSum[64], sDen[64];
    const int tid = threadIdx.x;
    const int tx = tid & 15, ty = tid >> 4;

    for (int i = tid; i < 64 * 64; i += 256)
        sKV[i] = g_kv[h * QK * Vv + i];
    if (tid < 64) sSum[tid] = g_sumk[h * QK + tid];
    for (int i = tid; i < 64 * 64; i += 256) {
        int r = tileR + (i >> 6);
        sQ[i] = (r < n) ? qp[(size_t)r * QK + (i & 63)] : 0.f;
    }
    __syncthreads();

    if (tid < 64) {
        float d = 0.f;
        #pragma unroll
        for (int c = 0; c < 64; c++) d = fmaf(sQ[tid * 64 + c], sSum[c], d);
        sDen[tid] = (d == 0.f) ? 1e-6f : d;
    }
    __syncthreads();

    float acc[16];
    #pragma unroll
    for (int i = 0; i < 16; i++) acc[i] = 0.f;
    #pragma unroll
    for (int k = 0; k < 64; k++) {
        float qv[4];
        #pragma unroll
        for (int i = 0; i < 4; i++) qv[i] = sQ[(ty * 4 + i) * 64 + k];
        float wv[4];
        #pragma unroll
        for (int j = 0; j < 4; j++) wv[j] = sKV[k * 64 + tx * 4 + j];
        #pragma unroll
        for (int i = 0; i < 4; i++)
            #pragma unroll
            for (int j = 0; j < 4; j++)
                acc[i * 4 + j] = fmaf(qv[i], wv[j], acc[i * 4 + j]);
    }

    #pragma unroll
    for (int i = 0; i < 4; i++) {
        int gr = tileR + ty * 4 + i;
        if (gr >= n) continue;
        float invd = 1.f / sDen[ty * 4 + i];
        #pragma unroll
        for (int j = 0; j < 4; j++)
            g_cat[(size_t)gr * CAT + h * Vv + tx * 4 + j] = acc[i * 4 + j] * invd;
    }
}

// ---------------------------------------------------------------------------
// psi: 64 rows/block, 256 thr, 96KB smem
// ---------------------------------------------------------------------------
__global__ void __launch_bounds__(256, 2) psi_tc_kernel(
    const float* __restrict__ bp0v, const float* __restrict__ bp1v,
    const float* __restrict__ mask, float* __restrict__ out, int n)
{
    extern __shared__ uint32_t sm[];
    uint32_t* sA = sm;            // A chunk (layer1) / A2 (layer2)
    uint32_t* sW = sm + 16384;

    const int tileR = blockIdx.x * 64;
    const int tid = threadIdx.x, w = tid >> 5, l = tid & 31;
    const int g = l >> 2, q4 = l & 3;

    // ---- layer 1: H[64,256] = cat[64,512] @ Wp0 ----
    float c1[4][4][4];
    #pragma unroll
    for (int a = 0; a < 4; a++)
        #pragma unroll
        for (int b = 0; b < 4; b++)
            #pragma unroll
            for (int c = 0; c < 4; c++) c1[a][b][c] = 0.f;

    for (int kc = 0; kc < 4; kc++) {
        __syncthreads();
        stage_A64x128(sA, g_cat, CAT, tileR, kc * 128, n, tid);
        for (int wc = 0; wc < 4; wc++) {
            __syncthreads();
            const uint32_t* srcw = g_p0s + (size_t)(kc * 4 + wc) * 8192;  // 2 kt x 32 nt
            #pragma unroll
            for (int e = tid * 4; e < 8192; e += 1024)
                *(uint4*)(sW + e) = *(const uint4*)(srcw + e);
            __syncthreads();
            #pragma unroll
            for (int kt2 = 0; kt2 < 2; kt2++) {
                int ktl = wc * 2 + kt2;   // local kt within staged A chunk
                uint2 bh[4], bl[4];
                #pragma unroll
                for (int j = 0; j < 4; j++) {
                    const uint32_t* bb = sW + (kt2 * 32 + w * 4 + j) * 128 + l * 2;
                    bh[j] = *(const uint2*)bb;
                    bl[j] = *(const uint2*)(bb + 64);
                }
                #pragma unroll
                for (int mt = 0; mt < 4; mt++) {
                    const uint32_t* ab = sA + (mt * 8 + ktl) * 256 + l * 4;
                    uint4 ah = *(const uint4*)ab;
                    uint4 al = *(const uint4*)(ab + 128);
                    #pragma unroll
                    for (int j = 0; j < 4; j++) {
                        mmabf(c1[mt][j], ah, bh[j]);
                        mmabf(c1[mt][j], al, bh[j]);
                        mmabf(c1[mt][j], ah, bl[j]);
                    }
                }
            }
        }
    }

    // ---- epilogue L1 -> A2 frags ----
    __syncthreads();
    #pragma unroll
    for (int mt = 0; mt < 4; mt++)
        #pragma unroll
        for (int j = 0; j < 4; j++) {
            int col0 = w * 32 + j * 8 + 2 * q4;
            float bv0 = bp0v[col0], bv1 = bp0v[col0 + 1];
            float v00 = fmaxf(c1[mt][j][0] + bv0, 0.f);
            float v01 = fmaxf(c1[mt][j][1] + bv1, 0.f);
            float v10 = fmaxf(c1[mt][j][2] + bv0, 0.f);
            float v11 = fmaxf(c1[mt][j][3] + bv1, 0.f);
            uint32_t h0, l0v, h1, l1v;
            split_pair(v00, v01, h0, l0v);
            split_pair(v10, v11, h1, l1v);
            int kt2 = w * 2 + (j >> 1);
            int rb = (j & 1) * 2;
            uint32_t* tb = sA + (mt * 16 + kt2) * 256 + l * 4;
            tb[rb]         = h0;
            tb[rb + 1]     = h1;
            tb[128 + rb]     = l0v;
            tb[128 + rb + 1] = l1v;
        }

    // ---- layer 2: out[64,128] = H[64,256] @ Wp1 ----
    float c2[4][2][4];
    #pragma unroll
    for (int a = 0; a < 4; a++)
        #pragma unroll
        for (int b = 0; b < 2; b++)
            #pragma unroll
            for (int c = 0; c < 4; c++) c2[a][b][c] = 0.f;

    for (int kc = 0; kc < 4; kc++) {
        __syncthreads();
        const uint32_t* srcw = g_p1s + (size_t)kc * 8192;   // 4 kt x 16 nt
        #pragma unroll
        for (int e = tid * 4; e < 8192; e += 1024)
            *(uint4*)(sW + e) = *(const uint4*)(srcw + e);
        __syncthreads();
        #pragma unroll
        for (int kt = 0; kt < 4; kt++) {
            int ktg = kc * 4 + kt;
            uint2 bh[2], bl[2];
            #pragma unroll
            for (int jn = 0; jn < 2; jn++) {
                const uint32_t* bb = sW + (kt * 16 + w * 2 + jn) * 128 + l * 2;
                bh[jn] = *(const uint2*)bb;
                bl[jn] = *(const uint2*)(bb + 64);
            }
            #pragma unroll
            for (int mt = 0; mt < 4; mt++) {
                const uint32_t* ab = sA + (mt * 16 + ktg) * 256 + l * 4;
                uint4 ah = *(const uint4*)ab;
                uint4 al = *(const uint4*)(ab + 128);
                #pragma unroll
                for (int jn = 0; jn < 2; jn++) {
                    mmabf(c2[mt][jn], ah, bh[jn]);
                    mmabf(c2[mt][jn], al, bh[jn]);
                    mmabf(c2[mt][jn], ah, bl[jn]);
                }
            }
        }
    }

    // ---- epilogue L2 ----
    #pragma unroll
    for (int jn = 0; jn < 2; jn++) {
        int col0 = (w * 2 + jn) * 8 + 2 * q4;
        float bb0 = bp1v[col0], bb1 = bp1v[col0 + 1];
        #pragma unroll
        for (int mt = 0; mt < 4; mt++)
            #pragma unroll
            for (int half = 0; half < 2; half++) {
                int gr = tileR + mt * 16 + g + half * 8;
                if (gr >= n) continue;
                float m = mask[gr];
                float v0 = (c2[mt][jn][half * 2 + 0] + bb0) * m;
                float v1 = (c2[mt][jn][half * 2 + 1] + bb1) * m;
                *(float2*)&out[(size_t)gr * OUT + col0] = make_float2(v0, v1);
            }
    }
}

// ---------------------------------------------------------------------------
extern "C" void kernel_launch(void* const* d_in, const int* in_sizes, int n_in,
                              void* d_out, int out_size)
{
    const float* x    = (const float*)d_in[0];
    const float* mask = (const float*)d_in[1];
    const float* Wq0 = (const float*)d_in[2];
    const float* bq0 = (const float*)d_in[3];
    const float* Wq1 = (const float*)d_in[4];
    const float* bq1 = (const float*)d_in[5];
    const float* Wk0 = (const float*)d_in[6];
    const float* bk0 = (const float*)d_in[7];
    const float* Wk1 = (const float*)d_in[8];
    const float* bk1 = (const float*)d_in[9];
    const float* Wv0 = (const float*)d_in[10];
    const float* bv0 = (const float*)d_in[11];
    const float* Wv1 = (const float*)d_in[12];
    const float* bv1 = (const float*)d_in[13];
    const float* Wp0 = (const float*)d_in[14];
    const float* bp0 = (const float*)d_in[15];
    const float* Wp1 = (const float*)d_in[16];
    const float* bp1 = (const float*)d_in[17];
    float* out = (float*)d_out;

    const int n = in_sizes[0] / Dm;
    const int tiles64 = (n + 63) / 64;
    const int nch = (n + CHUNK - 1) / CHUNK;

    static int attr_done = 0;
    if (!attr_done) {
        cudaFuncSetAttribute(mlp_tc_kernel,
            cudaFuncAttributeMaxDynamicSharedMemorySize, 96 * 1024);
        cudaFuncSetAttribute(psi_tc_kernel,
            cudaFuncAttributeMaxDynamicSharedMemorySize, 96 * 1024);
        attr_done = 1;
    }

    prep_weights_kernel<<<dim3(128, 50), 256>>>(Wq0, Wq1, Wk0, Wk1, Wv0, Wv1, Wp0, Wp1);
    mlp_tc_kernel<<<dim3(tiles64, Hh, 3), 256, 96 * 1024>>>(
        x, mask, bq0, bq1, bk0, bk1, bv0, bv1, n);
    kv_partial_kernel<<<dim3(nch, Hh), 256>>>(n);
    kv_reduce_kernel<<<dim3(Hh, 33), 128>>>(nch);
    attn_out_kernel<<<dim3(tiles64, Hh), 256>>>(n);
    psi_tc_kernel<<<tiles64, 256, 96 * 1024>>>(bp0, bp1, mask, out, n);
}

// round 8
// speedup vs baseline: 5.2644x; 1.1987x over previous
#include <cuda_runtime.h>
#include <cuda_fp16.h>
#include <math.h>
#include <stdint.h>

// Problem constants (fixed shapes)
#define MAXN   100000
#define Dm     128
#define Hh     8
#define HID    256
#define QK     64
#define Vv     64
#define PSI    256
#define OUT    128
#define CAT    (Hh*Vv)   // 512
#define CHUNK  512
#define MAXCH  ((MAXN + CHUNK - 1) / CHUNK + 4)   // 200
#define RT     4         // 64-row sub-tiles per mlp block (256 rows/block)

// ---------------- device scratch (static, allocation-free) ----------------
__device__ __align__(16) float g_q[(size_t)Hh * MAXN * QK];
__device__ __align__(16) float g_k[(size_t)Hh * MAXN * QK];
__device__ __align__(16) float g_v[(size_t)Hh * MAXN * Vv];
__device__ __align__(16) float g_cat[(size_t)MAXN * CAT];
__device__ __align__(16) float g_kv[Hh * QK * Vv];
__device__ __align__(16) float g_sumk[Hh * QK];
__device__ __align__(16) float g_kvp[(size_t)Hh * MAXCH * QK * Vv];
__device__ __align__(16) float g_skp[(size_t)Hh * MAXCH * QK];

// fp16 weights in fragment-ready tile layout.
// Tile = 16(k) x 8(n): 32 lanes x 2 u32 = 64 u32 = 256B.
// Per lane l (g=l>>2, q4=l&3): reg0 = (W[k0+2q4, n0+g], W[k0+2q4+1, n0+g]),
// reg1 = same rows +8.  Tile order (kt, nt) row-major.
__device__ __align__(16) uint32_t g_w0s[24 * 8 * 32 * 64];    // K=128,N=256 per (proj,h)
__device__ __align__(16) uint32_t g_w1s[24 * 16 * 8 * 64];    // K=256,N=64
__device__ __align__(16) uint32_t g_p0s[32 * 32 * 64];        // K=512,N=256
__device__ __align__(16) uint32_t g_p1s[16 * 16 * 64];        // K=256,N=128

// ---------------------------------------------------------------------------
// fp16 2-term split: a = ah + al (exact to ~2^-22); packs pairs as half2.
__device__ __forceinline__ void split_pair_h(float a, float b, uint32_t& hi, uint32_t& lo) {
    __half ah = __float2half_rn(a), bh = __float2half_rn(b);
    float ar = a - __half2float(ah);
    float br = b - __half2float(bh);
    hi = ((uint32_t)__half_as_ushort(bh) << 16) | (uint32_t)__half_as_ushort(ah);
    __half al = __float2half_rn(ar), bl = __float2half_rn(br);
    lo = ((uint32_t)__half_as_ushort(bl) << 16) | (uint32_t)__half_as_ushort(al);
}

__device__ __forceinline__ uint32_t pack_h(float a, float b) {
    return ((uint32_t)__half_as_ushort(__float2half_rn(b)) << 16)
         | (uint32_t)__half_as_ushort(__float2half_rn(a));
}

__device__ __forceinline__ void mmah(float* c, const uint4& a, const uint2& b) {
    asm volatile(
        "mma.sync.aligned.m16n8k16.row.col.f32.f16.f16.f32 "
        "{%0,%1,%2,%3},{%4,%5,%6,%7},{%8,%9},{%0,%1,%2,%3};"
        : "+f"(c[0]), "+f"(c[1]), "+f"(c[2]), "+f"(c[3])
        : "r"(a.x), "r"(a.y), "r"(a.z), "r"(a.w), "r"(b.x), "r"(b.y));
}

// ---------------------------------------------------------------------------
// prep: fp16 weights into fragment tiles.  grid (128, 50), 256 thr
// ---------------------------------------------------------------------------
__global__ void prep_weights_kernel(
    const float* __restrict__ Wq0, const float* __restrict__ Wq1,
    const float* __restrict__ Wk0, const float* __restrict__ Wk1,
    const float* __restrict__ Wv0, const float* __restrict__ Wv1,
    const float* __restrict__ Wp0, const float* __restrict__ Wp1)
{
    int seg = blockIdx.y;
    const float* src; uint32_t* dst; int K, N;
    if (seg < 24) {
        int p = seg >> 3, h = seg & 7;
        src = (p == 0 ? Wq0 : p == 1 ? Wk0 : Wv0) + (size_t)h * 128 * 256;
        dst = g_w0s + (size_t)seg * (8 * 32 * 64); K = 128; N = 256;
    } else if (seg < 48) {
        int s = seg - 24; int p = s >> 3, h = s & 7;
        src = (p == 0 ? Wq1 : p == 1 ? Wk1 : Wv1) + (size_t)h * 256 * 64;
        dst = g_w1s + (size_t)s * (16 * 8 * 64); K = 256; N = 64;
    } else if (seg == 48) { src = Wp0; dst = g_p0s; K = 512; N = 256; }
    else                  { src = Wp1; dst = g_p1s; K = 256; N = 128; }

    int nslots = (K >> 4) * (N >> 3) * 32;
    int s = blockIdx.x * 256 + threadIdx.x;
    if (s >= nslots) return;
    int tile = s >> 5, l = s & 31;
    int ntT = N >> 3;
    int kt = tile / ntT, nt = tile % ntT;
    int g = l >> 2, q4 = l & 3;
    int k0 = kt * 16 + 2 * q4, nn = nt * 8 + g;
    uint32_t* t = dst + (size_t)tile * 64;
    t[l * 2]     = pack_h(src[(size_t)k0 * N + nn],       src[(size_t)(k0 + 1) * N + nn]);
    t[l * 2 + 1] = pack_h(src[(size_t)(k0 + 8) * N + nn], src[(size_t)(k0 + 9) * N + nn]);
}

// ---------------------------------------------------------------------------
// Stage a 64x128 fp32 chunk into A-fragment tiles (fp16 hi/lo, 2-term).
// A tile = 256 u32: hi at lane*4+reg, lo at +128.
// ---------------------------------------------------------------------------
__device__ __forceinline__ void stage_A64x128(
    uint32_t* sA, const float* __restrict__ src, size_t rowStride,
    int tileR, int colOff, int n, int tid, int nthreads)
{
    for (int e = tid; e < 64 * 64; e += nthreads) {
        int r = e >> 6, cp = e & 63;
        int c = cp * 2;
        int gr = tileR + r;
        float x0 = 0.f, x1 = 0.f;
        if (gr < n) {
            const float* p = src + (size_t)gr * rowStride + colOff + c;
            x0 = p[0]; x1 = p[1];
        }
        uint32_t hi, lo;
        split_pair_h(x0, x1, hi, lo);
        int mt = r >> 4, kt = c >> 4, rr = r & 15, kk = c & 15;
        int lane = (rr & 7) * 4 + ((kk & 7) >> 1);
        int reg  = (kk >= 8 ? 2 : 0) + (rr >= 8 ? 1 : 0);
        uint32_t* tb = sA + (mt * 8 + kt) * 256 + lane * 4 + reg;
        tb[0]   = hi;
        tb[128] = lo;
    }
}

// ---------------------------------------------------------------------------
// mlp: weights fully smem-resident (96KB), 256 rows/block in 4 sub-tiles.
//   grid (ceil(n/256), H, 3), 256 thr, 160KB smem
// smem u32 map: sW0 [0,16384) sW1 [16384,24576) sA [24576,40960)
// ---------------------------------------------------------------------------
__global__ void __launch_bounds__(256, 1) mlp_tc_kernel(
    const float* __restrict__ x, const float* __restrict__ mask,
    const float* __restrict__ bq0, const float* __restrict__ bq1,
    const float* __restrict__ bk0, const float* __restrict__ bk1,
    const float* __restrict__ bv0, const float* __restrict__ bv1,
    int n)
{
    extern __shared__ uint32_t sm[];
    uint32_t* sW0 = sm;
    uint32_t* sW1 = sm + 16384;
    uint32_t* sA  = sm + 24576;

    const int h = blockIdx.y, proj = blockIdx.z;
    const int seg = proj * 8 + h;
    const float* b0 = (proj == 0 ? bq0 : proj == 1 ? bk0 : bv0) + h * HID;
    const float* b1 = (proj == 0 ? bq1 : proj == 1 ? bk1 : bv1) + h * QK;
    float* outBase = (proj == 0) ? g_q : (proj == 1) ? g_k : g_v;

    const int tid = threadIdx.x, w = tid >> 5, l = tid & 31;
    const int g = l >> 2, q4 = l & 3;

    // stage all weights once per block
    {
        const uint4* s0 = (const uint4*)(g_w0s + (size_t)seg * 16384);
        const uint4* s1 = (const uint4*)(g_w1s + (size_t)seg * 8192);
        uint4* d0 = (uint4*)sW0;
        uint4* d1 = (uint4*)sW1;
        #pragma unroll 4
        for (int i = tid; i < 4096; i += 256) d0[i] = s0[i];
        #pragma unroll 2
        for (int i = tid; i < 2048; i += 256) d1[i] = s1[i];
    }

    for (int rt = 0; rt < RT; rt++) {
        int tileR = (blockIdx.x * RT + rt) * 64;
        if (tileR >= n) break;
        __syncthreads();   // weights staged / previous sub-tile done reading sA
        stage_A64x128(sA, x, Dm, tileR, 0, n, tid, 256);
        __syncthreads();

        // ---- layer 1: C[64,256] = X[64,128] @ W0 (2-term fp16) ----
        // warp w covers N cols [w*32, w*32+32) as 4 n8-tiles
        float c1[4][4][4];
        #pragma unroll
        for (int a = 0; a < 4; a++)
            #pragma unroll
            for (int b = 0; b < 4; b++)
                #pragma unroll
                for (int c = 0; c < 4; c++) c1[a][b][c] = 0.f;

        #pragma unroll
        for (int kt = 0; kt < 8; kt++) {
            uint2 bv[4];
            #pragma unroll
            for (int j = 0; j < 4; j++)
                bv[j] = *(const uint2*)(sW0 + (kt * 32 + w * 4 + j) * 64 + l * 2);
            #pragma unroll
            for (int mt = 0; mt < 4; mt++) {
                const uint32_t* ab = sA + (mt * 8 + kt) * 256 + l * 4;
                uint4 ah = *(const uint4*)ab;
                uint4 al = *(const uint4*)(ab + 128);
                #pragma unroll
                for (int j = 0; j < 4; j++) {
                    mmah(c1[mt][j], ah, bv[j]);
                    mmah(c1[mt][j], al, bv[j]);
                }
            }
        }
        __syncthreads();   // all A1 reads done before A2 overwrite

        // ---- epilogue L1: bias+relu, split, write A2 frags ----
        #pragma unroll
        for (int mt = 0; mt < 4; mt++)
            #pragma unroll
            for (int j = 0; j < 4; j++) {
                int col0 = w * 32 + j * 8 + 2 * q4;
                float bv0 = b0[col0], bv1 = b0[col0 + 1];
                float v00 = fmaxf(c1[mt][j][0] + bv0, 0.f);
                float v01 = fmaxf(c1[mt][j][1] + bv1, 0.f);
                float v10 = fmaxf(c1[mt][j][2] + bv0, 0.f);
                float v11 = fmaxf(c1[mt][j][3] + bv1, 0.f);
                uint32_t h0, l0v, h1, l1v;
                split_pair_h(v00, v01, h0, l0v);
                split_pair_h(v10, v11, h1, l1v);
                int kt2 = w * 2 + (j >> 1);
                int rb = (j & 1) * 2;
                uint32_t* tb = sA + (mt * 16 + kt2) * 256 + l * 4;
                tb[rb]           = h0;
                tb[rb + 1]       = h1;
                tb[128 + rb]     = l0v;
                tb[128 + rb + 1] = l1v;
            }
        __syncthreads();

        // ---- layer 2: out[64,64] = H[64,256] @ W1 (2-term fp16) ----
        // warp w -> 2 m-tiles (w>>2)*2+{0,1}, 2 n-tiles (w&3)*2+{0,1}
        const int mtb = (w >> 2) * 2, ntb = (w & 3) * 2;
        float c2[2][2][4];
        #pragma unroll
        for (int a = 0; a < 2; a++)
            #pragma unroll
            for (int b = 0; b < 2; b++)
                #pragma unroll
                for (int c = 0; c < 4; c++) c2[a][b][c] = 0.f;

        #pragma unroll
        for (int kt = 0; kt < 16; kt++) {
            uint2 bv[2];
            #pragma unroll
            for (int jn = 0; jn < 2; jn++)
                bv[jn] = *(const uint2*)(sW1 + (kt * 8 + ntb + jn) * 64 + l * 2);
            #pragma unroll
            for (int mi = 0; mi < 2; mi++) {
                const uint32_t* ab = sA + ((mtb + mi) * 16 + kt) * 256 + l * 4;
                uint4 ah = *(const uint4*)ab;
                uint4 al = *(const uint4*)(ab + 128);
                #pragma unroll
                for (int jn = 0; jn < 2; jn++) {
                    mmah(c2[mi][jn], ah, bv[jn]);
                    mmah(c2[mi][jn], al, bv[jn]);
                }
            }
        }

        // ---- epilogue L2: bias, mask, phi, store ----
        #pragma unroll
        for (int mi = 0; mi < 2; mi++)
            #pragma unroll
            for (int jn = 0; jn < 2; jn++) {
                int col0 = (ntb + jn) * 8 + 2 * q4;
                float bb0 = b1[col0], bb1 = b1[col0 + 1];
                #pragma unroll
                for (int half = 0; half < 2; half++) {
                    int gr = tileR + (mtb + mi) * 16 + g + half * 8;
                    if (gr >= n) continue;
                    float m = mask[gr];
                    float v0 = (c2[mi][jn][half * 2 + 0] + bb0) * m;
                    float v1 = (c2[mi][jn][half * 2 + 1] + bb1) * m;
                    if (proj < 2) {
                        v0 = (v0 > 0.f) ? (v0 + 1.f) : __expf(v0);
                        v1 = (v1 > 0.f) ? (v1 + 1.f) : __expf(v1);
                    }
                    *(float2*)&outBase[((size_t)h * n + gr) * QK + col0] = make_float2(v0, v1);
                }
            }
    }
}

// ---------------------------------------------------------------------------
// kv partial / reduce / attn (fp32, unchanged proven path)
// ---------------------------------------------------------------------------
__global__ void kv_partial_kernel(int n)
{
    const int h = blockIdx.y;
    const int ch = blockIdx.x;
    const int chunk0 = ch * CHUNK;
    const int end = min(chunk0 + CHUNK, n);
    const float* kp = g_k + (size_t)h * n * QK;
    const float* vp = g_v + (size_t)h * n * Vv;

    __shared__ float sK[32 * 64], sV[32 * 64];
    const int tid = threadIdx.x;
    const int tx = tid & 15, ty = tid >> 4;

    float acc[16];
    #pragma unroll
    for (int i = 0; i < 16; i++) acc[i] = 0.f;
    float sumAcc = 0.f;

    for (int t0 = chunk0; t0 < end; t0 += 32) {
        __syncthreads();
        for (int i = tid; i < 32 * 64; i += 256) {
            int r = t0 + (i >> 6);
            int c = i & 63;
            if (r < end) { sK[i] = kp[(size_t)r * QK + c]; sV[i] = vp[(size_t)r * Vv + c]; }
            else         { sK[i] = 0.f; sV[i] = 0.f; }
        }
        __syncthreads();
        #pragma unroll
        for (int r = 0; r < 32; r++) {
            float kk[4], vv[4];
            #pragma unroll
            for (int i = 0; i < 4; i++) kk[i] = sK[r * 64 + ty * 4 + i];
            #pragma unroll
            for (int j = 0; j < 4; j++) vv[j] = sV[r * 64 + tx * 4 + j];
            #pragma unroll
            for (int i = 0; i < 4; i++)
                #pragma unroll
                for (int j = 0; j < 4; j++)
                    acc[i * 4 + j] = fmaf(kk[i], vv[j], acc[i * 4 + j]);
        }
        if (tid < 64) {
            #pragma unroll
            for (int r = 0; r < 32; r++) sumAcc += sK[r * 64 + tid];
        }
    }

    float* kvp = g_kvp + ((size_t)h * MAXCH + ch) * (QK * Vv);
    #pragma unroll
    for (int i = 0; i < 4; i++)
        #pragma unroll
        for (int j = 0; j < 4; j++)
            kvp[(ty * 4 + i) * 64 + tx * 4 + j] = acc[i * 4 + j];
    if (tid < 64)
        g_skp[((size_t)h * MAXCH + ch) * QK + tid] = sumAcc;
}

// grid (Hh, 33), 128 threads
__global__ void kv_reduce_kernel(int nch)
{
    const int h = blockIdx.x;
    const int c = blockIdx.y * 128 + threadIdx.x;
    if (c < QK * Vv) {
        float s = 0.f;
        for (int j = 0; j < nch; j++)
            s += g_kvp[((size_t)h * MAXCH + j) * (QK * Vv) + c];
        g_kv[h * QK * Vv + c] = s;
    } else if (c < QK * Vv + QK) {
        int cc = c - QK * Vv;
        float s = 0.f;
        for (int j = 0; j < nch; j++)
            s += g_skp[((size_t)h * MAXCH + j) * QK + cc];
        g_sumk[h * QK + cc] = s;
    }
}

__global__ void attn_out_kernel(int n)
{
    const int h = blockIdx.y;
    const int tileR = blockIdx.x * 64;
    const float* qp = g_q + (size_t)h * n * QK;

    __shared__ float sQ[64 * 64], sKV[64 * 64], sSum[64], sDen[64];
    const int tid = threadIdx.x;
    const int tx = tid & 15, ty = tid >> 4;

    for (int i = tid; i < 64 * 64; i += 256)
        sKV[i] = g_kv[h * QK * Vv + i];
    if (tid < 64) sSum[tid] = g_sumk[h * QK + tid];
    for (int i = tid; i < 64 * 64; i += 256) {
        int r = tileR + (i >> 6);
        sQ[i] = (r < n) ? qp[(size_t)r * QK + (i & 63)] : 0.f;
    }
    __syncthreads();

    if (tid < 64) {
        float d = 0.f;
        #pragma unroll
        for (int c = 0; c < 64; c++) d = fmaf(sQ[tid * 64 + c], sSum[c], d);
        sDen[tid] = (d == 0.f) ? 1e-6f : d;
    }
    __syncthreads();

    float acc[16];
    #pragma unroll
    for (int i = 0; i < 16; i++) acc[i] = 0.f;
    #pragma unroll
    for (int k = 0; k < 64; k++) {
        float qv[4];
        #pragma unroll
        for (int i = 0; i < 4; i++) qv[i] = sQ[(ty * 4 + i) * 64 + k];
        float wv[4];
        #pragma unroll
        for (int j = 0; j < 4; j++) wv[j] = sKV[k * 64 + tx * 4 + j];
        #pragma unroll
        for (int i = 0; i < 4; i++)
            #pragma unroll
            for (int j = 0; j < 4; j++)
                acc[i * 4 + j] = fmaf(qv[i], wv[j], acc[i * 4 + j]);
    }

    #pragma unroll
    for (int i = 0; i < 4; i++) {
        int gr = tileR + ty * 4 + i;
        if (gr >= n) continue;
        float invd = 1.f / sDen[ty * 4 + i];
        #pragma unroll
        for (int j = 0; j < 4; j++)
            g_cat[(size_t)gr * CAT + h * Vv + tx * 4 + j] = acc[i * 4 + j] * invd;
    }
}

// ---------------------------------------------------------------------------
// psi: 64 rows/block, 256 thr, 80KB smem (chunked weights, 2-term fp16)
// smem u32 map: sA [0,16384), sW [16384,20480)
// ---------------------------------------------------------------------------
__global__ void __launch_bounds__(256, 2) psi_tc_kernel(
    const float* __restrict__ bp0v, const float* __restrict__ bp1v,
    const float* __restrict__ mask, float* __restrict__ out, int n)
{
    extern __shared__ uint32_t smu[];
    uint32_t* sA = smu;
    uint32_t* sW = smu + 16384;

    const int tileR = blockIdx.x * 64;
    const int tid = threadIdx.x, w = tid >> 5, l = tid & 31;
    const int g = l >> 2, q4 = l & 3;

    // ---- layer 1: H[64,256] = cat[64,512] @ Wp0 ----
    float c1[4][4][4];
    #pragma unroll
    for (int a = 0; a < 4; a++)
        #pragma unroll
        for (int b = 0; b < 4; b++)
            #pragma unroll
            for (int c = 0; c < 4; c++) c1[a][b][c] = 0.f;

    for (int kc = 0; kc < 4; kc++) {
        __syncthreads();
        stage_A64x128(sA, g_cat, CAT, tileR, kc * 128, n, tid, 256);
        for (int wc = 0; wc < 4; wc++) {
            __syncthreads();
            const uint32_t* srcw = g_p0s + (size_t)(kc * 4 + wc) * 4096;  // 2kt x 32nt x 64
            #pragma unroll
            for (int e = tid * 4; e < 4096; e += 1024)
                *(uint4*)(sW + e) = *(const uint4*)(srcw + e);
            __syncthreads();
            #pragma unroll
            for (int kt2 = 0; kt2 < 2; kt2++) {
                int ktl = wc * 2 + kt2;
                uint2 bv[4];
                #pragma unroll
                for (int j = 0; j < 4; j++)
                    bv[j] = *(const uint2*)(sW + (kt2 * 32 + w * 4 + j) * 64 + l * 2);
                #pragma unroll
                for (int mt = 0; mt < 4; mt++) {
                    const uint32_t* ab = sA + (mt * 8 + ktl) * 256 + l * 4;
                    uint4 ah = *(const uint4*)ab;
                    uint4 al = *(const uint4*)(ab + 128);
                    #pragma unroll
                    for (int j = 0; j < 4; j++) {
                        mmah(c1[mt][j], ah, bv[j]);
                        mmah(c1[mt][j], al, bv[j]);
                    }
                }
            }
        }
    }

    __syncthreads();
    // ---- epilogue L1 -> A2 frags ----
    #pragma unroll
    for (int mt = 0; mt < 4; mt++)
        #pragma unroll
        for (int j = 0; j < 4; j++) {
            int col0 = w * 32 + j * 8 + 2 * q4;
            float bv0 = bp0v[col0], bv1 = bp0v[col0 + 1];
            float v00 = fmaxf(c1[mt][j][0] + bv0, 0.f);
            float v01 = fmaxf(c1[mt][j][1] + bv1, 0.f);
            float v10 = fmaxf(c1[mt][j][2] + bv0, 0.f);
            float v11 = fmaxf(c1[mt][j][3] + bv1, 0.f);
            uint32_t h0, l0v, h1, l1v;
            split_pair_h(v00, v01, h0, l0v);
            split_pair_h(v10, v11, h1, l1v);
            int kt2 = w * 2 + (j >> 1);
            int rb = (j & 1) * 2;
            uint32_t* tb = sA + (mt * 16 + kt2) * 256 + l * 4;
            tb[rb]           = h0;
            tb[rb + 1]       = h1;
            tb[128 + rb]     = l0v;
            tb[128 + rb + 1] = l1v;
        }

    // ---- layer 2: out[64,128] = H[64,256] @ Wp1 ----
    float c2[4][2][4];
    #pragma unroll
    for (int a = 0; a < 4; a++)
        #pragma unroll
        for (int b = 0; b < 2; b++)
            #pragma unroll
            for (int c = 0; c < 4; c++) c2[a][b][c] = 0.f;

    for (int kc = 0; kc < 4; kc++) {
        __syncthreads();
        const uint32_t* srcw = g_p1s + (size_t)kc * 4096;   // 4kt x 16nt x 64
        #pragma unroll
        for (int e = tid * 4; e < 4096; e += 1024)
            *(uint4*)(sW + e) = *(const uint4*)(srcw + e);
        __syncthreads();
        #pragma unroll
        for (int kt = 0; kt < 4; kt++) {
            int ktg = kc * 4 + kt;
            uint2 bv[2];
            #pragma unroll
            for (int jn = 0; jn < 2; jn++)
                bv[jn] = *(const uint2*)(sW + (kt * 16 + w * 2 + jn) * 64 + l * 2);
            #pragma unroll
            for (int mt = 0; mt < 4; mt++) {
                const uint32_t* ab = sA + (mt * 16 + ktg) * 256 + l * 4;
                uint4 ah = *(const uint4*)ab;
                uint4 al = *(const uint4*)(ab + 128);
                #pragma unroll
                for (int jn = 0; jn < 2; jn++) {
                    mmah(c2[mt][jn], ah, bv[jn]);
                    mmah(c2[mt][jn], al, bv[jn]);
                }
            }
        }
    }

    // ---- epilogue L2 ----
    #pragma unroll
    for (int jn = 0; jn < 2; jn++) {
        int col0 = (w * 2 + jn) * 8 + 2 * q4;
        float bb0 = bp1v[col0], bb1 = bp1v[col0 + 1];
        #pragma unroll
        for (int mt = 0; mt < 4; mt++)
            #pragma unroll
            for (int half = 0; half < 2; half++) {
                int gr = tileR + mt * 16 + g + half * 8;
                if (gr >= n) continue;
                float m = mask[gr];
                float v0 = (c2[mt][jn][half * 2 + 0] + bb0) * m;
                float v1 = (c2[mt][jn][half * 2 + 1] + bb1) * m;
                *(float2*)&out[(size_t)gr * OUT + col0] = make_float2(v0, v1);
            }
    }
}

// ---------------------------------------------------------------------------
extern "C" void kernel_launch(void* const* d_in, const int* in_sizes, int n_in,
                              void* d_out, int out_size)
{
    const float* x    = (const float*)d_in[0];
    const float* mask = (const float*)d_in[1];
    const float* Wq0 = (const float*)d_in[2];
    const float* bq0 = (const float*)d_in[3];
    const float* Wq1 = (const float*)d_in[4];
    const float* bq1 = (const float*)d_in[5];
    const float* Wk0 = (const float*)d_in[6];
    const float* bk0 = (const float*)d_in[7];
    const float* Wk1 = (const float*)d_in[8];
    const float* bk1 = (const float*)d_in[9];
    const float* Wv0 = (const float*)d_in[10];
    const float* bv0 = (const float*)d_in[11];
    const float* Wv1 = (const float*)d_in[12];
    const float* bv1 = (const float*)d_in[13];
    const float* Wp0 = (const float*)d_in[14];
    const float* bp0 = (const float*)d_in[15];
    const float* Wp1 = (const float*)d_in[16];
    const float* bp1 = (const float*)d_in[17];
    float* out = (float*)d_out;

    const int n = in_sizes[0] / Dm;
    const int tiles64 = (n + 63) / 64;
    const int tilesMlp = (n + 255) / 256;
    const int nch = (n + CHUNK - 1) / CHUNK;

    static int attr_done = 0;
    if (!attr_done) {
        cudaFuncSetAttribute(mlp_tc_kernel,
            cudaFuncAttributeMaxDynamicSharedMemorySize, 160 * 1024);
        cudaFuncSetAttribute(psi_tc_kernel,
            cudaFuncAttributeMaxDynamicSharedMemorySize, 80 * 1024);
        attr_done = 1;
    }

    prep_weights_kernel<<<dim3(128, 50), 256>>>(Wq0, Wq1, Wk0, Wk1, Wv0, Wv1, Wp0, Wp1);
    mlp_tc_kernel<<<dim3(tilesMlp, Hh, 3), 256, 160 * 1024>>>(
        x, mask, bq0, bq1, bk0, bk1, bv0, bv1, n);
    kv_partial_kernel<<<dim3(nch, Hh), 256>>>(n);
    kv_reduce_kernel<<<dim3(Hh, 33), 128>>>(nch);
    attn_out_kernel<<<dim3(tiles64, Hh), 256>>>(n);
    psi_tc_kernel<<<tiles64, 256, 80 * 1024>>>(bp0, bp1, mask, out, n);
}